// round 14
// baseline (speedup 1.0000x reference)
#include <cuda_runtime.h>
#include <cuda_fp16.h>
#include <cstdint>

// ============================================================================
// BatchConv2D 3x3 via mma.sync f16 (2-term: x_fp16 * (wh + wl)), fp32 accum.
// Warp-specialized: CTA = 320 thr. Warps 0-7 compute (batch, x-half 128px,
// 8 rows, 32 oc; 4 steps x 2 rows; warp = row x 32px x 32oc). Warps 8-9 are
// producers staging input rows into a 6-slot fp16 ring, synced by per-slot
// full/empty mbarriers. Weights staged once by compute warps.
// ============================================================================

#define BATCH 32
#define CH    32
#define HH    256
#define WW    256
#define HW    (HH * WW)

#define A_STR   136                 // u32 per (slot,j) row; conflict-free LDS
#define SLOT_W  (16 * A_STR)        // 2176 u32 per row slot (8704 B)
#define NSLOT   6
#define WQ_STR  148                 // uint2 per oc; conflict-free LDS.64

#define SMEM_BIAS 0                                   // 128 B
#define SMEM_WQ   128                                 // 37888 B
#define SMEM_RING (SMEM_WQ + 37888)                   // 38016
#define SMEM_MBAR (SMEM_RING + NSLOT * SLOT_W * 4)    // 90240: 12 x 8 B
#define SMEM_TOTAL (SMEM_MBAR + 96)                   // 90336 B

#define MBARRIER_INIT(addr, count) \
    asm volatile("mbarrier.init.shared.b64 [%0], %1;" \
                 :: "r"((uint32_t)(addr)), "r"((uint32_t)(count)) : "memory")

#define MBARRIER_ARRIVE(addr) \
    asm volatile("mbarrier.arrive.shared.b64 _, [%0];" \
                 :: "r"((uint32_t)(addr)) : "memory")

#define MBARRIER_WAIT_PARITY(addr, parity) do { \
    uint32_t _mbar = (uint32_t)(addr); \
    uint32_t _par  = (uint32_t)(parity); \
    asm volatile( \
        "{\n\t" \
        ".reg .pred P1;\n\t" \
        "WAIT_LOOP_%=:\n\t" \
        "mbarrier.try_wait.parity.acquire.cta.shared::cta.b64 P1, [%0], %1, 0x989680;\n\t" \
        "@P1 bra.uni WAIT_DONE_%=;\n\t" \
        "bra.uni WAIT_LOOP_%=;\n\t" \
        "WAIT_DONE_%=:\n\t" \
        "}" :: "r"(_mbar), "r"(_par) : "memory"); \
} while (0)

__device__ __forceinline__ void mma_f16(float* d, const uint32_t* a,
                                        uint32_t b0, uint32_t b1) {
    asm volatile(
        "mma.sync.aligned.m16n8k16.row.col.f32.f16.f16.f32 "
        "{%0,%1,%2,%3}, {%4,%5,%6,%7}, {%8,%9}, {%0,%1,%2,%3};\n"
        : "+f"(d[0]), "+f"(d[1]), "+f"(d[2]), "+f"(d[3])
        : "r"(a[0]), "r"(a[1]), "r"(a[2]), "r"(a[3]), "r"(b0), "r"(b1));
}

// One warp stages one whole input row gy into ring slot rs.
__device__ __forceinline__ void stage_row_warp(uint32_t* rs,
                                               const float* __restrict__ xb,
                                               int gy, int x0, int lane) {
    const bool yok = (unsigned)gy < (unsigned)HH;
    const float* rowp = xb + (size_t)(yok ? gy : 0) * WW;
#pragma unroll 1
    for (int j = 0; j < 16; ++j) {
        const float* pj = rowp + (size_t)(2 * j) * HW;
#pragma unroll
        for (int ii = 0; ii < 5; ++ii) {
            const int i = lane + ii * 32;
            if (i < 130) {
                const int gx = x0 - 1 + i;
                const bool ok = yok && ((unsigned)gx < (unsigned)WW);
                const float* px = pj + (ok ? gx : 0);
                const float v0 = ok ? px[0] : 0.0f;
                const float v1 = ok ? px[HW] : 0.0f;
                const __half2 h2 = __floats2half2_rn(v0, v1);
                rs[j * A_STR + i] = *reinterpret_cast<const uint32_t*>(&h2);
            }
        }
    }
}

__global__ void __launch_bounds__(320, 2)
batch_conv3x3_ws_kernel(const float* __restrict__ x,
                        const float* __restrict__ w,
                        const float* __restrict__ bias,
                        float* __restrict__ out)
{
    extern __shared__ char smem[];
    float*    bias_s = reinterpret_cast<float*>(smem + SMEM_BIAS);
    uint2*    wq     = reinterpret_cast<uint2*>(smem + SMEM_WQ);
    uint32_t* ring   = reinterpret_cast<uint32_t*>(smem + SMEM_RING);

    uint32_t smem_base;
    asm("{ .reg .u64 t; cvta.to.shared.u64 t, %1; cvt.u32.u64 %0, t; }"
        : "=r"(smem_base) : "l"(smem));
    const uint32_t mb_full0  = smem_base + SMEM_MBAR;       // full[0..5]
    const uint32_t mb_empty0 = smem_base + SMEM_MBAR + 48;  // empty[0..5]

    const int tid  = threadIdx.x;       // 0..319
    const int lane = tid & 31;
    const int wid  = tid >> 5;          // 0..9
    const int xh   = blockIdx.x;        // 0..1
    const int yg   = blockIdx.y;        // 0..31
    const int b    = blockIdx.z;        // 0..31
    const int x0   = xh * 128;
    const int y0   = yg * 8;

    if (tid == 0) {
#pragma unroll
        for (int i = 0; i < NSLOT; ++i) {
            MBARRIER_INIT(mb_full0 + i * 8, 1);
            MBARRIER_INIT(mb_empty0 + i * 8, 1);
        }
    }
    __syncthreads();    // only full-block barrier (all 320 threads, once)

    const float* xb = x + (size_t)b * CH * HW;

    // =================== producer warps (8, 9) ===================
    if (wid >= 8) {
        const int p = wid - 8;          // 0 or 1
#pragma unroll 1
        for (int idx = p; idx < 10; idx += 2) {   // row gy = y0 - 1 + idx
            const int slot = (idx < NSLOT) ? idx : idx - NSLOT;
            MBARRIER_WAIT_PARITY(mb_empty0 + slot * 8, (idx < NSLOT) ? 1 : 0);
            stage_row_warp(ring + slot * SLOT_W, xb, y0 - 1 + idx, x0, lane);
            __syncwarp();
            if (lane == 0) MBARRIER_ARRIVE(mb_full0 + slot * 8);
        }
        return;
    }

    // =================== compute warps (0-7) ===================
    if (tid < CH) bias_s[tid] = bias[b * CH + tid];

    // weights -> SMEM: wq[oc*WQ_STR + tap*16 + kp] = (hi_pair, lo_pair)
    const float* wg = w + (size_t)b * (CH * CH * 9);
    for (int idx = tid; idx < CH * 9 * 16; idx += 256) {
        const int oc  = idx / 144;
        const int rem = idx - oc * 144;
        const int tap = rem >> 4;
        const int kp  = rem & 15;
        const float v0 = wg[(oc * CH + 2 * kp) * 9 + tap];
        const float v1 = wg[(oc * CH + 2 * kp + 1) * 9 + tap];
        const __half h0 = __float2half_rn(v0);
        const __half h1 = __float2half_rn(v1);
        const __half l0 = __float2half_rn(v0 - __half2float(h0));
        const __half l1 = __float2half_rn(v1 - __half2float(h1));
        const uint32_t hiw =
            ((uint32_t)__half_as_ushort(h1) << 16) | __half_as_ushort(h0);
        const uint32_t low =
            ((uint32_t)__half_as_ushort(l1) << 16) | __half_as_ushort(l0);
        wq[oc * WQ_STR + rem] = make_uint2(hiw, low);
    }
    asm volatile("bar.sync 1, 256;" ::: "memory");   // weights visible

    const int g    = lane >> 2;        // 0..7
    const int tg   = lane & 3;         // 0..3
    const int p0   = (wid & 3) * 32;   // pixel base within 128
    const int rsel = wid >> 2;         // 0/1: row within the pair

#pragma unroll 1
    for (int s = 0; s < 4; ++s) {
        const int lr = 2 * s + rsel;   // local row 0..7

        // wait for newly needed ring rows (idx = global-row - y0 + 1)
        if (s == 0) {
#pragma unroll
            for (int k = 0; k < 4; ++k)
                MBARRIER_WAIT_PARITY(mb_full0 + k * 8, 0);
        } else {
            const int ia = 2 * s + 2, ib = 2 * s + 3;
            MBARRIER_WAIT_PARITY(mb_full0 + ((ia < NSLOT) ? ia : ia - NSLOT) * 8,
                                 (ia < NSLOT) ? 0 : 1);
            MBARRIER_WAIT_PARITY(mb_full0 + ((ib < NSLOT) ? ib : ib - NSLOT) * 8,
                                 (ib < NSLOT) ? 0 : 1);
        }

        float acc[2][4][4];
#pragma unroll
        for (int nb = 0; nb < 4; ++nb) {
            const float b0v = bias_s[nb * 8 + tg * 2];
            const float b1v = bias_s[nb * 8 + tg * 2 + 1];
#pragma unroll
            for (int t = 0; t < 2; ++t) {
                acc[t][nb][0] = b0v; acc[t][nb][1] = b1v;
                acc[t][nb][2] = b0v; acc[t][nb][3] = b1v;
            }
        }

#pragma unroll
        for (int tap = 0; tap < 9; ++tap) {
            const int dy = tap / 3, dx = tap % 3;
            int sl = lr + dy;                    // ring idx of row lr-1+dy
            if (sl >= NSLOT) sl -= NSLOT;
            const uint32_t* rs = ring + sl * SLOT_W;
#pragma unroll
            for (int half = 0; half < 2; ++half) {
                const int rj  = (half * 8 + tg) * A_STR;
                const int rj4 = rj + 4 * A_STR;
                uint32_t a[2][4];
#pragma unroll
                for (int t = 0; t < 2; ++t) {
                    const int pb = p0 + t * 16 + g + dx;
                    a[t][0] = rs[rj + pb];   a[t][1] = rs[rj + pb + 8];
                    a[t][2] = rs[rj4 + pb];  a[t][3] = rs[rj4 + pb + 8];
                }
                const int wbse = tap * 16 + half * 8 + tg;
                uint2 q0[4], q1[4];
#pragma unroll
                for (int nb = 0; nb < 4; ++nb) {
                    const int base = (nb * 8 + g) * WQ_STR + wbse;
                    q0[nb] = wq[base];
                    q1[nb] = wq[base + 4];
                }
#pragma unroll
                for (int nb = 0; nb < 4; ++nb) {
                    mma_f16(acc[0][nb], a[0], q0[nb].x, q1[nb].x);
                    mma_f16(acc[1][nb], a[1], q0[nb].x, q1[nb].x);
                }
#pragma unroll
                for (int nb = 0; nb < 4; ++nb) {
                    mma_f16(acc[0][nb], a[0], q0[nb].y, q1[nb].y);
                    mma_f16(acc[1][nb], a[1], q0[nb].y, q1[nb].y);
                }
            }
        }

        // store this row's 32px x 32oc tile
        float* ob = out + (size_t)b * CH * HW + (size_t)(y0 + lr) * WW + x0;
#pragma unroll
        for (int t = 0; t < 2; ++t) {
            const int p = p0 + t * 16 + g;
#pragma unroll
            for (int nb = 0; nb < 4; ++nb) {
                const int oc0 = nb * 8 + tg * 2;
                ob[(size_t)oc0 * HW + p]           = acc[t][nb][0];
                ob[(size_t)(oc0 + 1) * HW + p]     = acc[t][nb][1];
                ob[(size_t)oc0 * HW + p + 8]       = acc[t][nb][2];
                ob[(size_t)(oc0 + 1) * HW + p + 8] = acc[t][nb][3];
            }
        }

        // release the two ring rows that are now dead (idx 2s, 2s+1 -> slots)
        asm volatile("bar.sync 1, 256;" ::: "memory");
        if (tid == 0 && s < 3) {
            MBARRIER_ARRIVE(mb_empty0 + (2 * s) * 8);
            MBARRIER_ARRIVE(mb_empty0 + (2 * s + 1) * 8);
        }
    }
}

extern "C" void kernel_launch(void* const* d_in, const int* in_sizes, int n_in,
                              void* d_out, int out_size)
{
    const float* x    = (const float*)d_in[0];
    const float* w    = (const float*)d_in[1];
    const float* bias = (const float*)d_in[2];
    float* out        = (float*)d_out;

    cudaFuncSetAttribute(batch_conv3x3_ws_kernel,
                         cudaFuncAttributeMaxDynamicSharedMemorySize,
                         SMEM_TOTAL);

    dim3 grid(2, HH / 8, BATCH);   // 2048 CTAs
    batch_conv3x3_ws_kernel<<<grid, 320, SMEM_TOTAL>>>(x, w, bias, out);
}

// round 15
// speedup vs baseline: 1.3639x; 1.3639x over previous
#include <cuda_runtime.h>
#include <cuda_fp16.h>
#include <cstdint>

// ============================================================================
// BatchConv2D 3x3 via mma.sync f16 (2-term: x_fp16 * (wh + wl)), fp32 accum.
// CTA = 256 thr (8 warps): (batch, x-half 128px, 8 rows), all 32 oc.
// 4 steps x 2 rows; warp = one row x 32px x 32oc (m32n32). K = 288 per term.
// Ring: 4 row-slots of fp16x2 ci-pair words (stride 136 -> conflict-free LDS.32).
// Weights: (hi,lo) interleaved uint2, oc stride 148 -> conflict-free LDS.64.
// R15: occupancy 3 CTAs/SM (SMEM 72.8KB < 76KB; launch_bounds(256,3)),
// div-free staging loop.
// ============================================================================

#define BATCH 32
#define CH    32
#define HH    256
#define WW    256
#define HW    (HH * WW)

#define A_STR   136                 // u32 per (slot,j) row; 136 % 32 == 8
#define SLOT_W  (16 * A_STR)        // 2176 u32 per row slot
#define WQ_STR  148                 // uint2 per oc; 148 % 16 == 4

#define SMEM_BIAS 0                                   // 128 B
#define SMEM_WQ   128                                 // 32*148*8 = 37888 B
#define SMEM_RING (SMEM_WQ + 37888)                   // 38016
#define SMEM_TOTAL (SMEM_RING + 4 * SLOT_W * 4)       // 72832 B

__device__ __forceinline__ void mma_f16(float* d, const uint32_t* a,
                                        uint32_t b0, uint32_t b1) {
    asm volatile(
        "mma.sync.aligned.m16n8k16.row.col.f32.f16.f16.f32 "
        "{%0,%1,%2,%3}, {%4,%5,%6,%7}, {%8,%9}, {%0,%1,%2,%3};\n"
        : "+f"(d[0]), "+f"(d[1]), "+f"(d[2]), "+f"(d[3])
        : "r"(a[0]), "r"(a[1]), "r"(a[2]), "r"(a[3]), "r"(b0), "r"(b1));
}

// Stage input row gy into ring slot (gy+4)&3 as packed fp16x2 ci-pairs.
// Div-free: thread handles j = tid>>4, i = (tid&15) + 16k, k = 0..8.
__device__ __forceinline__ void stage_row(uint32_t* ring,
                                          const float* __restrict__ xb,
                                          int gy, int x0, int tid) {
    uint32_t* rs = ring + ((gy + 4) & 3) * SLOT_W;
    const bool yok = (unsigned)gy < (unsigned)HH;
    const float* rowp = xb + (size_t)(yok ? gy : 0) * WW;
    const int j  = tid >> 4;            // 0..15
    const int i0 = tid & 15;            // 0..15
    const float* pj = rowp + (size_t)(2 * j) * HW;
    uint32_t* rj = rs + j * A_STR;
#pragma unroll
    for (int k = 0; k < 9; ++k) {
        const int i = i0 + 16 * k;
        if (i < 130) {
            const int gx = x0 - 1 + i;
            const bool ok = yok && ((unsigned)gx < (unsigned)WW);
            const float* px = pj + (ok ? gx : 0);
            const float v0 = ok ? px[0] : 0.0f;
            const float v1 = ok ? px[HW] : 0.0f;
            const __half2 h2 = __floats2half2_rn(v0, v1);
            rj[i] = *reinterpret_cast<const uint32_t*>(&h2);
        }
    }
}

__global__ void __launch_bounds__(256, 3)
batch_conv3x3_f16o_kernel(const float* __restrict__ x,
                          const float* __restrict__ w,
                          const float* __restrict__ bias,
                          float* __restrict__ out)
{
    extern __shared__ char smem[];
    float*    bias_s = reinterpret_cast<float*>(smem + SMEM_BIAS);
    uint2*    wq     = reinterpret_cast<uint2*>(smem + SMEM_WQ);
    uint32_t* ring   = reinterpret_cast<uint32_t*>(smem + SMEM_RING);

    const int tid  = threadIdx.x;       // 0..255
    const int lane = tid & 31;
    const int wid  = tid >> 5;          // 0..7
    const int xh   = blockIdx.x;        // 0..1
    const int yg   = blockIdx.y;        // 0..31
    const int b    = blockIdx.z;        // 0..31
    const int x0   = xh * 128;
    const int y0   = yg * 8;

    if (tid < CH) bias_s[tid] = bias[b * CH + tid];

    // ---- weights -> SMEM: wq[oc*WQ_STR + tap*16 + kp] = (hi_pair, lo_pair)
    //      hi = fp16(w), lo = fp16(w - (float)hi)  (exact 2-term split)
    const float* wg = w + (size_t)b * (CH * CH * 9);
    for (int idx = tid; idx < CH * 9 * 16; idx += 256) {
        const int oc  = idx / 144;
        const int rem = idx - oc * 144;
        const int tap = rem >> 4;
        const int kp  = rem & 15;
        const float v0 = wg[(oc * CH + 2 * kp) * 9 + tap];
        const float v1 = wg[(oc * CH + 2 * kp + 1) * 9 + tap];
        const __half h0 = __float2half_rn(v0);
        const __half h1 = __float2half_rn(v1);
        const __half l0 = __float2half_rn(v0 - __half2float(h0));
        const __half l1 = __float2half_rn(v1 - __half2float(h1));
        const uint32_t hiw =
            ((uint32_t)__half_as_ushort(h1) << 16) | __half_as_ushort(h0);
        const uint32_t low =
            ((uint32_t)__half_as_ushort(l1) << 16) | __half_as_ushort(l0);
        wq[oc * WQ_STR + rem] = make_uint2(hiw, low);
    }

    // ---- initial ring fill: input rows y0-1 .. y0+2
    const float* xb = x + (size_t)b * CH * HW;
    stage_row(ring, xb, y0 - 1, x0, tid);
    stage_row(ring, xb, y0,     x0, tid);
    stage_row(ring, xb, y0 + 1, x0, tid);
    stage_row(ring, xb, y0 + 2, x0, tid);
    __syncthreads();

    const int g    = lane >> 2;        // 0..7
    const int tg   = lane & 3;         // 0..3
    const int p0   = (wid & 3) * 32;   // pixel base within 128
    const int rsel = wid >> 2;         // 0/1: row within the pair

#pragma unroll 1
    for (int s = 0; s < 4; ++s) {
        const int row = y0 + 2 * s + rsel;

        float acc[2][4][4];
#pragma unroll
        for (int nb = 0; nb < 4; ++nb) {
            const float b0v = bias_s[nb * 8 + tg * 2];
            const float b1v = bias_s[nb * 8 + tg * 2 + 1];
#pragma unroll
            for (int t = 0; t < 2; ++t) {
                acc[t][nb][0] = b0v; acc[t][nb][1] = b1v;
                acc[t][nb][2] = b0v; acc[t][nb][3] = b1v;
            }
        }

#pragma unroll
        for (int tap = 0; tap < 9; ++tap) {
            const int dy = tap / 3, dx = tap % 3;
            const uint32_t* rs = ring + ((row - 1 + dy + 4) & 3) * SLOT_W;
#pragma unroll
            for (int half = 0; half < 2; ++half) {
                // A fragments: 8 LDS.32
                const int rj  = (half * 8 + tg) * A_STR;
                const int rj4 = rj + 4 * A_STR;
                uint32_t a[2][4];
#pragma unroll
                for (int t = 0; t < 2; ++t) {
                    const int pb = p0 + t * 16 + g + dx;
                    a[t][0] = rs[rj + pb];   a[t][1] = rs[rj + pb + 8];
                    a[t][2] = rs[rj4 + pb];  a[t][3] = rs[rj4 + pb + 8];
                }
                // B fragments: 8 LDS.64 ((hi,lo) pairs for kp and kp+4)
                const int wbse = tap * 16 + half * 8 + tg;
                uint2 q0[4], q1[4];
#pragma unroll
                for (int nb = 0; nb < 4; ++nb) {
                    const int base = (nb * 8 + g) * WQ_STR + wbse;
                    q0[nb] = wq[base];
                    q1[nb] = wq[base + 4];
                }
                // 16 MMAs: 2 rounds over 8 independent accumulators
#pragma unroll
                for (int nb = 0; nb < 4; ++nb) {
                    mma_f16(acc[0][nb], a[0], q0[nb].x, q1[nb].x);
                    mma_f16(acc[1][nb], a[1], q0[nb].x, q1[nb].x);
                }
#pragma unroll
                for (int nb = 0; nb < 4; ++nb) {
                    mma_f16(acc[0][nb], a[0], q0[nb].y, q1[nb].y);
                    mma_f16(acc[1][nb], a[1], q0[nb].y, q1[nb].y);
                }
            }
        }

        // ---- store this row's 32px x 32oc tile
        float* ob = out + (size_t)b * CH * HW + (size_t)row * WW + x0;
#pragma unroll
        for (int t = 0; t < 2; ++t) {
            const int p = p0 + t * 16 + g;
#pragma unroll
            for (int nb = 0; nb < 4; ++nb) {
                const int oc0 = nb * 8 + tg * 2;
                ob[(size_t)oc0 * HW + p]           = acc[t][nb][0];
                ob[(size_t)(oc0 + 1) * HW + p]     = acc[t][nb][1];
                ob[(size_t)oc0 * HW + p + 8]       = acc[t][nb][2];
                ob[(size_t)(oc0 + 1) * HW + p + 8] = acc[t][nb][3];
            }
        }

        // ---- ring advance
        __syncthreads();
        if (s < 3) {
            stage_row(ring, xb, y0 + 2 * s + 3, x0, tid);
            stage_row(ring, xb, y0 + 2 * s + 4, x0, tid);
            __syncthreads();
        }
    }
}

extern "C" void kernel_launch(void* const* d_in, const int* in_sizes, int n_in,
                              void* d_out, int out_size)
{
    const float* x    = (const float*)d_in[0];
    const float* w    = (const float*)d_in[1];
    const float* bias = (const float*)d_in[2];
    float* out        = (float*)d_out;

    cudaFuncSetAttribute(batch_conv3x3_f16o_kernel,
                         cudaFuncAttributeMaxDynamicSharedMemorySize,
                         SMEM_TOTAL);

    dim3 grid(2, HH / 8, BATCH);   // 2048 CTAs
    batch_conv3x3_f16o_kernel<<<grid, 256, SMEM_TOTAL>>>(x, w, bias, out);
}

// round 17
// speedup vs baseline: 2.7236x; 1.9970x over previous
#include <cuda_runtime.h>
#include <cuda_fp16.h>
#include <cstdint>

// ============================================================================
// BatchConv2D 3x3 via mma.sync f16 (1-term: fp16(x) * fp16(w)), fp32 accum.
// CTA = 256 thr (8 warps): (batch, x-half 128px, 8 rows), all 32 oc.
// 4 steps x 2 rows; warp = one row x 32px x 32oc (m32n32). K = 288.
// Ring: 4 row-slots of fp16x2 ci-pair words (stride 136 -> conflict-free LDS.32).
// Weights: fp16 pairs, oc stride 148 words -> conflict-free LDS.32.
// Error: x-round + w-round (u=2^-11 each) -> aggregate rel_err ~3e-4 < 1e-3.
// Occupancy 3 CTAs/SM (SMEM 53.9KB).
// ============================================================================

#define BATCH 32
#define CH    32
#define HH    256
#define WW    256
#define HW    (HH * WW)

#define A_STR   136                 // u32 per (slot,j) row; 136 % 32 == 8
#define SLOT_W  (16 * A_STR)        // 2176 u32 per row slot
#define WQ_STR  148                 // u32 per oc; 148 % 32 == 20

#define SMEM_BIAS 0                                   // 128 B
#define SMEM_WQ   128                                 // 32*148*4 = 18944 B
#define SMEM_RING (SMEM_WQ + 18944)                   // 19072
#define SMEM_TOTAL (SMEM_RING + 4 * SLOT_W * 4)       // 53888 B

__device__ __forceinline__ void mma_f16(float* d, const uint32_t* a,
                                        uint32_t b0, uint32_t b1) {
    asm volatile(
        "mma.sync.aligned.m16n8k16.row.col.f32.f16.f16.f32 "
        "{%0,%1,%2,%3}, {%4,%5,%6,%7}, {%8,%9}, {%0,%1,%2,%3};\n"
        : "+f"(d[0]), "+f"(d[1]), "+f"(d[2]), "+f"(d[3])
        : "r"(a[0]), "r"(a[1]), "r"(a[2]), "r"(a[3]), "r"(b0), "r"(b1));
}

// Stage input row gy into ring slot (gy+4)&3 as packed fp16x2 ci-pairs.
// Div-free: thread handles j = tid>>4, i = (tid&15) + 16k, k = 0..8.
__device__ __forceinline__ void stage_row(uint32_t* ring,
                                          const float* __restrict__ xb,
                                          int gy, int x0, int tid) {
    uint32_t* rs = ring + ((gy + 4) & 3) * SLOT_W;
    const bool yok = (unsigned)gy < (unsigned)HH;
    const float* rowp = xb + (size_t)(yok ? gy : 0) * WW;
    const int j  = tid >> 4;            // 0..15
    const int i0 = tid & 15;            // 0..15
    const float* pj = rowp + (size_t)(2 * j) * HW;
    uint32_t* rj = rs + j * A_STR;
#pragma unroll
    for (int k = 0; k < 9; ++k) {
        const int i = i0 + 16 * k;
        if (i < 130) {
            const int gx = x0 - 1 + i;
            const bool ok = yok && ((unsigned)gx < (unsigned)WW);
            const float* px = pj + (ok ? gx : 0);
            const float v0 = ok ? px[0] : 0.0f;
            const float v1 = ok ? px[HW] : 0.0f;
            const __half2 h2 = __floats2half2_rn(v0, v1);
            rj[i] = *reinterpret_cast<const uint32_t*>(&h2);
        }
    }
}

__global__ void __launch_bounds__(256, 3)
batch_conv3x3_f16s_kernel(const float* __restrict__ x,
                          const float* __restrict__ w,
                          const float* __restrict__ bias,
                          float* __restrict__ out)
{
    extern __shared__ char smem[];
    float*    bias_s = reinterpret_cast<float*>(smem + SMEM_BIAS);
    uint32_t* wq     = reinterpret_cast<uint32_t*>(smem + SMEM_WQ);
    uint32_t* ring   = reinterpret_cast<uint32_t*>(smem + SMEM_RING);

    const int tid  = threadIdx.x;       // 0..255
    const int lane = tid & 31;
    const int wid  = tid >> 5;          // 0..7
    const int xh   = blockIdx.x;        // 0..1
    const int yg   = blockIdx.y;        // 0..31
    const int b    = blockIdx.z;        // 0..31
    const int x0   = xh * 128;
    const int y0   = yg * 8;

    if (tid < CH) bias_s[tid] = bias[b * CH + tid];

    // ---- weights -> SMEM: wq[oc*WQ_STR + tap*16 + kp] = fp16 pair (ci 2kp, 2kp+1)
    const float* wg = w + (size_t)b * (CH * CH * 9);
    for (int idx = tid; idx < CH * 9 * 16; idx += 256) {
        const int oc  = idx / 144;
        const int rem = idx - oc * 144;
        const int tap = rem >> 4;
        const int kp  = rem & 15;
        const float v0 = wg[(oc * CH + 2 * kp) * 9 + tap];
        const float v1 = wg[(oc * CH + 2 * kp + 1) * 9 + tap];
        const __half2 h2 = __floats2half2_rn(v0, v1);
        wq[oc * WQ_STR + rem] = *reinterpret_cast<const uint32_t*>(&h2);
    }

    // ---- initial ring fill: input rows y0-1 .. y0+2
    const float* xb = x + (size_t)b * CH * HW;
    stage_row(ring, xb, y0 - 1, x0, tid);
    stage_row(ring, xb, y0,     x0, tid);
    stage_row(ring, xb, y0 + 1, x0, tid);
    stage_row(ring, xb, y0 + 2, x0, tid);
    __syncthreads();

    const int g    = lane >> 2;        // 0..7
    const int tg   = lane & 3;         // 0..3
    const int p0   = (wid & 3) * 32;   // pixel base within 128
    const int rsel = wid >> 2;         // 0/1: row within the pair

#pragma unroll 1
    for (int s = 0; s < 4; ++s) {
        const int row = y0 + 2 * s + rsel;

        float acc[2][4][4];
#pragma unroll
        for (int nb = 0; nb < 4; ++nb) {
            const float b0v = bias_s[nb * 8 + tg * 2];
            const float b1v = bias_s[nb * 8 + tg * 2 + 1];
#pragma unroll
            for (int t = 0; t < 2; ++t) {
                acc[t][nb][0] = b0v; acc[t][nb][1] = b1v;
                acc[t][nb][2] = b0v; acc[t][nb][3] = b1v;
            }
        }

#pragma unroll
        for (int tap = 0; tap < 9; ++tap) {
            const int dy = tap / 3, dx = tap % 3;
            const uint32_t* rs = ring + ((row - 1 + dy + 4) & 3) * SLOT_W;
#pragma unroll
            for (int half = 0; half < 2; ++half) {
                // A fragments: 8 LDS.32
                const int rj  = (half * 8 + tg) * A_STR;
                const int rj4 = rj + 4 * A_STR;
                uint32_t a[2][4];
#pragma unroll
                for (int t = 0; t < 2; ++t) {
                    const int pb = p0 + t * 16 + g + dx;
                    a[t][0] = rs[rj + pb];   a[t][1] = rs[rj + pb + 8];
                    a[t][2] = rs[rj4 + pb];  a[t][3] = rs[rj4 + pb + 8];
                }
                // B fragments: 8 LDS.32 (fp16 pairs for kp and kp+4)
                const int wbse = tap * 16 + half * 8 + tg;
                uint32_t q0[4], q1[4];
#pragma unroll
                for (int nb = 0; nb < 4; ++nb) {
                    const int base = (nb * 8 + g) * WQ_STR + wbse;
                    q0[nb] = wq[base];
                    q1[nb] = wq[base + 4];
                }
                // 8 MMAs over 8 independent accumulators
#pragma unroll
                for (int nb = 0; nb < 4; ++nb) {
                    mma_f16(acc[0][nb], a[0], q0[nb], q1[nb]);
                    mma_f16(acc[1][nb], a[1], q0[nb], q1[nb]);
                }
            }
        }

        // ---- store this row's 32px x 32oc tile
        float* ob = out + (size_t)b * CH * HW + (size_t)row * WW + x0;
#pragma unroll
        for (int t = 0; t < 2; ++t) {
            const int p = p0 + t * 16 + g;
#pragma unroll
            for (int nb = 0; nb < 4; ++nb) {
                const int oc0 = nb * 8 + tg * 2;
                ob[(size_t)oc0 * HW + p]           = acc[t][nb][0];
                ob[(size_t)(oc0 + 1) * HW + p]     = acc[t][nb][1];
                ob[(size_t)oc0 * HW + p + 8]       = acc[t][nb][2];
                ob[(size_t)(oc0 + 1) * HW + p + 8] = acc[t][nb][3];
            }
        }

        // ---- ring advance
        __syncthreads();
        if (s < 3) {
            stage_row(ring, xb, y0 + 2 * s + 3, x0, tid);
            stage_row(ring, xb, y0 + 2 * s + 4, x0, tid);
            __syncthreads();
        }
    }
}

extern "C" void kernel_launch(void* const* d_in, const int* in_sizes, int n_in,
                              void* d_out, int out_size)
{
    const float* x    = (const float*)d_in[0];
    const float* w    = (const float*)d_in[1];
    const float* bias = (const float*)d_in[2];
    float* out        = (float*)d_out;

    cudaFuncSetAttribute(batch_conv3x3_f16s_kernel,
                         cudaFuncAttributeMaxDynamicSharedMemorySize,
                         SMEM_TOTAL);

    dim3 grid(2, HH / 8, BATCH);   // 2048 CTAs
    batch_conv3x3_f16s_kernel<<<grid, 256, SMEM_TOTAL>>>(x, w, bias, out);
}